// round 1
// baseline (speedup 1.0000x reference)
#include <cuda_runtime.h>
#include <math.h>

// Shapes (fixed for this problem)
#define BATCH 2
#define SEQ   2048
#define DMODEL 1024
#define HEADS 16
#define HDIM  64
#define MROWS (BATCH * SEQ)          // 4096
#define NQKV  (3 * DMODEL)           // 3072

// Scratch: qkv in [part(3)][B][H][S][Hd] layout, attention out in [B][H][S][Hd]
__device__ float g_qkv[(size_t)3 * BATCH * HEADS * SEQ * HDIM];   // 48 MB
__device__ float g_attn[(size_t)BATCH * HEADS * SEQ * HDIM];      // 16 MB

// ---------------------------------------------------------------------------
// Kernel 1: QKV GEMM. C[m,n] = sum_k X[m,k] * W[n,k] + bias[n]
// X: [4096,1024] row-major, W: [3072,1024] row-major.
// Output scattered into g_qkv[part][b][h][s][hd].
// Tile 128x128, K-tile 16, 256 threads, 8x8 per thread.
// ---------------------------------------------------------------------------
__global__ __launch_bounds__(256) void qkv_gemm_kernel(
    const float* __restrict__ X, const float* __restrict__ W,
    const float* __restrict__ bias)
{
    __shared__ float As[16][132];
    __shared__ float Bs[16][132];

    const int tid = threadIdx.x;
    const int tx = tid & 15;
    const int ty = tid >> 4;
    const int mBase = blockIdx.y * 128;
    const int nBase = blockIdx.x * 128;

    float acc[8][8];
#pragma unroll
    for (int i = 0; i < 8; i++)
#pragma unroll
        for (int j = 0; j < 8; j++) acc[i][j] = 0.0f;

    for (int kb = 0; kb < DMODEL; kb += 16) {
#pragma unroll
        for (int t = 0; t < 2; t++) {
            int idx = tid + t * 256;          // 0..511
            int row = idx >> 2;               // 0..127
            int quad = idx & 3;               // 0..3
            float4 a = *(const float4*)&X[(size_t)(mBase + row) * DMODEL + kb + quad * 4];
            As[quad * 4 + 0][row] = a.x;
            As[quad * 4 + 1][row] = a.y;
            As[quad * 4 + 2][row] = a.z;
            As[quad * 4 + 3][row] = a.w;
            float4 b = *(const float4*)&W[(size_t)(nBase + row) * DMODEL + kb + quad * 4];
            Bs[quad * 4 + 0][row] = b.x;
            Bs[quad * 4 + 1][row] = b.y;
            Bs[quad * 4 + 2][row] = b.z;
            Bs[quad * 4 + 3][row] = b.w;
        }
        __syncthreads();

#pragma unroll
        for (int k = 0; k < 16; k++) {
            float a[8], b[8];
            *(float4*)&a[0] = *(float4*)&As[k][ty * 4];
            *(float4*)&a[4] = *(float4*)&As[k][64 + ty * 4];
            *(float4*)&b[0] = *(float4*)&Bs[k][tx * 4];
            *(float4*)&b[4] = *(float4*)&Bs[k][64 + tx * 4];
#pragma unroll
            for (int i = 0; i < 8; i++)
#pragma unroll
                for (int j = 0; j < 8; j++)
                    acc[i][j] = fmaf(a[i], b[j], acc[i][j]);
        }
        __syncthreads();
    }

    // Epilogue: add bias, scatter to g_qkv[part][b][h][s][hd]
#pragma unroll
    for (int i = 0; i < 8; i++) {
        int m = mBase + ((i < 4) ? (ty * 4 + i) : (64 + ty * 4 + i - 4));
        int b = m >> 11;          // m / 2048
        int s = m & 2047;
#pragma unroll
        for (int j = 0; j < 8; j++) {
            int n = nBase + ((j < 4) ? (tx * 4 + j) : (64 + tx * 4 + j - 4));
            int part = n >> 10;
            int h = (n >> 6) & 15;
            int hd = n & 63;
            float v = acc[i][j] + bias[n];
            size_t off = ((size_t)((part * BATCH + b) * HEADS + h) * SEQ + s) * HDIM + hd;
            g_qkv[off] = v;
        }
    }
}

// ---------------------------------------------------------------------------
// Kernel 2: per-head LayerNorm over Hd=64, in place on q (part 0) and k (part 1).
// One warp per row; lane handles elements lane and lane+32.
// ---------------------------------------------------------------------------
__global__ __launch_bounds__(256) void ln_kernel(
    const float* __restrict__ qg, const float* __restrict__ qb,
    const float* __restrict__ kg, const float* __restrict__ kb)
{
    int warp = (blockIdx.x * blockDim.x + threadIdx.x) >> 5;
    int lane = threadIdx.x & 31;
    // total rows: 2 parts * B*H*S = 131072
    float* base = g_qkv + (size_t)warp * 64;
    int part = warp >> 16;  // 65536 rows per part
    const float* gamma = (part == 0) ? qg : kg;
    const float* beta  = (part == 0) ? qb : kb;

    float x0 = base[lane];
    float x1 = base[lane + 32];
    float s = x0 + x1;
#pragma unroll
    for (int o = 16; o >= 1; o >>= 1) s += __shfl_xor_sync(0xffffffffu, s, o);
    float mu = s * (1.0f / 64.0f);
    float d0 = x0 - mu, d1 = x1 - mu;
    float v = d0 * d0 + d1 * d1;
#pragma unroll
    for (int o = 16; o >= 1; o >>= 1) v += __shfl_xor_sync(0xffffffffu, v, o);
    float r = rsqrtf(v * (1.0f / 64.0f) + 1e-5f);
    base[lane]      = d0 * r * gamma[lane]      + beta[lane];
    base[lane + 32] = d1 * r * gamma[lane + 32] + beta[lane + 32];
}

// ---------------------------------------------------------------------------
// Kernel 3: flash attention, fp32, Hd=64.
// Grid: (S/64, B*H). Block: 256 threads (16x16).
// Q tile 64 rows (transposed in smem), K tiles of 64 keys (transposed),
// V tiles direct. P (softmaxed scores) overwrites the K buffer.
// Thread (tx,ty): score block rows ty*4.., cols tx*4..; O block rows ty*4..,
// dims tx*4.. Row stats reduced across the 16-lane tx group via shfl.
// ---------------------------------------------------------------------------
__global__ __launch_bounds__(256) void attn_kernel()
{
    __shared__ float Qt[64 * 64];   // [d][r]
    __shared__ float Kt[64 * 64];   // [d][c], reused as P[r][c]
    __shared__ float Vs[64 * 64];   // [c][d]

    const int tid = threadIdx.x;
    const int tx = tid & 15;
    const int ty = tid >> 4;
    const int bh = blockIdx.y;               // 0..31
    const int qbase = blockIdx.x * 64;

    const float* Qg = g_qkv + (size_t)(bh)      * (SEQ * HDIM);
    const float* Kg = g_qkv + (size_t)(32 + bh) * (SEQ * HDIM);
    const float* Vg = g_qkv + (size_t)(64 + bh) * (SEQ * HDIM);

    // Load Q tile transposed: Qt[d][r]
#pragma unroll
    for (int t = 0; t < 4; t++) {
        int idx = tid + t * 256;     // 0..1023
        int r = idx >> 2;            // 0..255? no: 1024/4 = 256... r in 0..255
        int quad = idx & 3;
        // 64 rows * 16 quads = 1024 float4; r = idx>>4? Recompute:
        // Use: r = idx / 16? We want 64 rows x 16 quads.
        r = idx >> 4;                // 0..63
        quad = idx & 15;             // 0..15
        float4 a = *(const float4*)&Qg[(size_t)(qbase + r) * HDIM + quad * 4];
        Qt[(quad * 4 + 0) * 64 + r] = a.x;
        Qt[(quad * 4 + 1) * 64 + r] = a.y;
        Qt[(quad * 4 + 2) * 64 + r] = a.z;
        Qt[(quad * 4 + 3) * 64 + r] = a.w;
    }

    float m_i[4], l_i[4], o[4][4];
#pragma unroll
    for (int i = 0; i < 4; i++) {
        m_i[i] = -1e30f;
        l_i[i] = 0.0f;
#pragma unroll
        for (int j = 0; j < 4; j++) o[i][j] = 0.0f;
    }
    __syncthreads();

    for (int kt = 0; kt < SEQ; kt += 64) {
        // Load K (transposed) and V tiles
#pragma unroll
        for (int t = 0; t < 4; t++) {
            int idx = tid + t * 256;
            int c = idx >> 4;        // 0..63
            int quad = idx & 15;
            float4 k4 = *(const float4*)&Kg[(size_t)(kt + c) * HDIM + quad * 4];
            Kt[(quad * 4 + 0) * 64 + c] = k4.x;
            Kt[(quad * 4 + 1) * 64 + c] = k4.y;
            Kt[(quad * 4 + 2) * 64 + c] = k4.z;
            Kt[(quad * 4 + 3) * 64 + c] = k4.w;
            float4 v4 = *(const float4*)&Vg[(size_t)(kt + c) * HDIM + quad * 4];
            *(float4*)&Vs[c * 64 + quad * 4] = v4;
        }
        __syncthreads();

        // S = Q @ K^T (scaled)
        float sc[4][4];
#pragma unroll
        for (int i = 0; i < 4; i++)
#pragma unroll
            for (int j = 0; j < 4; j++) sc[i][j] = 0.0f;

#pragma unroll 8
        for (int d = 0; d < 64; d++) {
            float4 k4 = *(float4*)&Kt[d * 64 + tx * 4];
#pragma unroll
            for (int i = 0; i < 4; i++) {
                float q = Qt[d * 64 + ty * 4 + i];
                sc[i][0] = fmaf(q, k4.x, sc[i][0]);
                sc[i][1] = fmaf(q, k4.y, sc[i][1]);
                sc[i][2] = fmaf(q, k4.z, sc[i][2]);
                sc[i][3] = fmaf(q, k4.w, sc[i][3]);
            }
        }

        // Online softmax update
#pragma unroll
        for (int i = 0; i < 4; i++) {
            float mx = sc[i][0];
            mx = fmaxf(mx, sc[i][1]);
            mx = fmaxf(mx, sc[i][2]);
            mx = fmaxf(mx, sc[i][3]);
            mx *= 0.125f;            // scale = 1/sqrt(64); fold into s below
#pragma unroll
            for (int j = 0; j < 4; j++) sc[i][j] *= 0.125f;
#pragma unroll
            for (int off = 8; off >= 1; off >>= 1)
                mx = fmaxf(mx, __shfl_xor_sync(0xffffffffu, mx, off));
            float mnew = fmaxf(m_i[i], mx);
            float alpha = __expf(m_i[i] - mnew);
            float rs = 0.0f;
#pragma unroll
            for (int j = 0; j < 4; j++) {
                float p = __expf(sc[i][j] - mnew);
                sc[i][j] = p;
                rs += p;
            }
#pragma unroll
            for (int off = 8; off >= 1; off >>= 1)
                rs += __shfl_xor_sync(0xffffffffu, rs, off);
            l_i[i] = l_i[i] * alpha + rs;
            m_i[i] = mnew;
#pragma unroll
            for (int j = 0; j < 4; j++) o[i][j] *= alpha;
        }
        __syncthreads();   // everyone done reading Kt

        // Write P over Kt as P[r][c]
#pragma unroll
        for (int i = 0; i < 4; i++) {
            float4 p4 = make_float4(sc[i][0], sc[i][1], sc[i][2], sc[i][3]);
            *(float4*)&Kt[(ty * 4 + i) * 64 + tx * 4] = p4;
        }
        __syncthreads();

        // O += P @ V
#pragma unroll 8
        for (int c = 0; c < 64; c++) {
            float4 v4 = *(float4*)&Vs[c * 64 + tx * 4];
#pragma unroll
            for (int i = 0; i < 4; i++) {
                float p = Kt[(ty * 4 + i) * 64 + c];
                o[i][0] = fmaf(p, v4.x, o[i][0]);
                o[i][1] = fmaf(p, v4.y, o[i][1]);
                o[i][2] = fmaf(p, v4.z, o[i][2]);
                o[i][3] = fmaf(p, v4.w, o[i][3]);
            }
        }
        __syncthreads();
    }

    // Normalize and write out
    float* Og = g_attn + (size_t)bh * (SEQ * HDIM);
#pragma unroll
    for (int i = 0; i < 4; i++) {
        float inv = 1.0f / l_i[i];
        float4 r = make_float4(o[i][0] * inv, o[i][1] * inv, o[i][2] * inv, o[i][3] * inv);
        *(float4*)&Og[(size_t)(qbase + ty * 4 + i) * HDIM + tx * 4] = r;
    }
}

// ---------------------------------------------------------------------------
// Kernel 4: projection GEMM. C[m,n] = sum_k A[m,k] * Wp[n,k] + bp[n]
// A[m,k] = g_attn[b][h][s][hd] with b=m/2048, s=m%2048, h=k/64, hd=k%64.
// Output to d_out[m*1024 + n].
// ---------------------------------------------------------------------------
__global__ __launch_bounds__(256) void proj_gemm_kernel(
    const float* __restrict__ Wp, const float* __restrict__ bp,
    float* __restrict__ out)
{
    __shared__ float As[16][132];
    __shared__ float Bs[16][132];

    const int tid = threadIdx.x;
    const int tx = tid & 15;
    const int ty = tid >> 4;
    const int mBase = blockIdx.y * 128;
    const int nBase = blockIdx.x * 128;

    float acc[8][8];
#pragma unroll
    for (int i = 0; i < 8; i++)
#pragma unroll
        for (int j = 0; j < 8; j++) acc[i][j] = 0.0f;

    for (int kb = 0; kb < DMODEL; kb += 16) {
#pragma unroll
        for (int t = 0; t < 2; t++) {
            int idx = tid + t * 256;
            int row = idx >> 2;
            int quad = idx & 3;
            int m = mBase + row;
            int k = kb + quad * 4;
            int b = m >> 11, s = m & 2047;
            int h = k >> 6, hd = k & 63;
            size_t aoff = ((size_t)(b * HEADS + h) * SEQ + s) * HDIM + hd;
            float4 a = *(const float4*)&g_attn[aoff];
            As[quad * 4 + 0][row] = a.x;
            As[quad * 4 + 1][row] = a.y;
            As[quad * 4 + 2][row] = a.z;
            As[quad * 4 + 3][row] = a.w;
            float4 bb = *(const float4*)&Wp[(size_t)(nBase + row) * DMODEL + k];
            Bs[quad * 4 + 0][row] = bb.x;
            Bs[quad * 4 + 1][row] = bb.y;
            Bs[quad * 4 + 2][row] = bb.z;
            Bs[quad * 4 + 3][row] = bb.w;
        }
        __syncthreads();

#pragma unroll
        for (int k = 0; k < 16; k++) {
            float a[8], b[8];
            *(float4*)&a[0] = *(float4*)&As[k][ty * 4];
            *(float4*)&a[4] = *(float4*)&As[k][64 + ty * 4];
            *(float4*)&b[0] = *(float4*)&Bs[k][tx * 4];
            *(float4*)&b[4] = *(float4*)&Bs[k][64 + tx * 4];
#pragma unroll
            for (int i = 0; i < 8; i++)
#pragma unroll
                for (int j = 0; j < 8; j++)
                    acc[i][j] = fmaf(a[i], b[j], acc[i][j]);
        }
        __syncthreads();
    }

#pragma unroll
    for (int i = 0; i < 8; i++) {
        int m = mBase + ((i < 4) ? (ty * 4 + i) : (64 + ty * 4 + i - 4));
#pragma unroll
        for (int j = 0; j < 8; j++) {
            int n = nBase + ((j < 4) ? (tx * 4 + j) : (64 + tx * 4 + j - 4));
            out[(size_t)m * DMODEL + n] = acc[i][j] + bp[n];
        }
    }
}

// ---------------------------------------------------------------------------
// Launch
// Inputs: 0:x 1:w_qkv 2:b_qkv 3:w_proj 4:b_proj 5:q_gamma 6:q_beta 7:k_gamma 8:k_beta
// ---------------------------------------------------------------------------
extern "C" void kernel_launch(void* const* d_in, const int* in_sizes, int n_in,
                              void* d_out, int out_size)
{
    const float* x      = (const float*)d_in[0];
    const float* w_qkv  = (const float*)d_in[1];
    const float* b_qkv  = (const float*)d_in[2];
    const float* w_proj = (const float*)d_in[3];
    const float* b_proj = (const float*)d_in[4];
    const float* q_g    = (const float*)d_in[5];
    const float* q_b    = (const float*)d_in[6];
    const float* k_g    = (const float*)d_in[7];
    const float* k_b    = (const float*)d_in[8];
    float* out = (float*)d_out;

    dim3 g1(NQKV / 128, MROWS / 128);   // (24, 32)
    qkv_gemm_kernel<<<g1, 256>>>(x, w_qkv, b_qkv);

    // 131072 rows, 8 warps per block
    ln_kernel<<<131072 / 8, 256>>>(q_g, q_b, k_g, k_b);

    dim3 g3(SEQ / 64, BATCH * HEADS);   // (32, 32)
    attn_kernel<<<g3, 256>>>();

    dim3 g4(DMODEL / 128, MROWS / 128); // (8, 32)
    proj_gemm_kernel<<<g4, 256>>>(w_proj, b_proj, out);
}

// round 3
// speedup vs baseline: 2.0099x; 2.0099x over previous
#include <cuda_runtime.h>
#include <math.h>
#include <stdint.h>

#define BATCH 2
#define SEQ   2048
#define DMODEL 1024
#define HEADS 16
#define HDIM  64
#define MROWS (BATCH * SEQ)          // 4096
#define NQKV  (3 * DMODEL)           // 3072

// Scratch: qkv in [part(3)][B*H][S][Hd] layout, attention out in [B*H][S][Hd]
__device__ float g_qkv[(size_t)3 * BATCH * HEADS * SEQ * HDIM];
__device__ float g_attn[(size_t)BATCH * HEADS * SEQ * HDIM];

__device__ __forceinline__ uint32_t f2tf(float x) {
    uint32_t r;
    asm("cvt.rna.tf32.f32 %0, %1;" : "=r"(r) : "f"(x));
    return r;
}
__device__ __forceinline__ float f2tf_f(float x) { return __uint_as_float(f2tf(x)); }

// D = A(16x8, row) * B(8x8, col) + D, tf32 inputs, fp32 accum
__device__ __forceinline__ void mma8(float* c, const uint32_t* a, const uint32_t* b) {
    asm volatile(
        "mma.sync.aligned.m16n8k8.row.col.f32.tf32.tf32.f32 "
        "{%0,%1,%2,%3}, {%4,%5,%6,%7}, {%8,%9}, {%0,%1,%2,%3};"
        : "+f"(c[0]), "+f"(c[1]), "+f"(c[2]), "+f"(c[3])
        : "r"(a[0]), "r"(a[1]), "r"(a[2]), "r"(a[3]), "r"(b[0]), "r"(b[1]));
}

// ---------------------------------------------------------------------------
// Kernel 1: QKV GEMM (tf32 tensor cores). C[m,n] = X[m,:]·W[n,:] + bias[n],
// scattered into g_qkv[part][b*16+h][s][hd].
// CTA tile 128x128, k-tile 32, 256 threads = 8 warps (4m x 2n), warp 32x64.
// ---------------------------------------------------------------------------
__global__ __launch_bounds__(256, 1) void qkv_gemm_tf32(
    const float* __restrict__ X, const float* __restrict__ W,
    const float* __restrict__ bias)
{
    __shared__ float As[32][136];   // [k][m]
    __shared__ float Bs[32][136];   // [k][n]

    const int tid = threadIdx.x;
    const int warp = tid >> 5;
    const int lane = tid & 31;
    const int g = lane >> 2;        // 0..7
    const int t = lane & 3;         // 0..3
    const int wm = (warp >> 1) * 32;
    const int wn = (warp & 1) * 64;
    const int mBase = blockIdx.y * 128;
    const int nBase = blockIdx.x * 128;

    float acc[2][8][4];
#pragma unroll
    for (int mt = 0; mt < 2; mt++)
#pragma unroll
        for (int nt = 0; nt < 8; nt++)
#pragma unroll
            for (int i = 0; i < 4; i++) acc[mt][nt][i] = 0.0f;

    float4 ra[4], rb[4];
    // prologue: load k-tile 0
#pragma unroll
    for (int t4 = 0; t4 < 4; t4++) {
        int idx = tid + t4 * 256;
        int row = idx & 127;
        int q = idx >> 7;
        ra[t4] = *(const float4*)&X[(size_t)(mBase + row) * DMODEL + q * 4];
        rb[t4] = *(const float4*)&W[(size_t)(nBase + row) * DMODEL + q * 4];
    }
#pragma unroll
    for (int t4 = 0; t4 < 4; t4++) {
        int idx = tid + t4 * 256;
        int row = idx & 127;
        int q = idx >> 7;
        As[q*4+0][row] = f2tf_f(ra[t4].x); As[q*4+1][row] = f2tf_f(ra[t4].y);
        As[q*4+2][row] = f2tf_f(ra[t4].z); As[q*4+3][row] = f2tf_f(ra[t4].w);
        Bs[q*4+0][row] = f2tf_f(rb[t4].x); Bs[q*4+1][row] = f2tf_f(rb[t4].y);
        Bs[q*4+2][row] = f2tf_f(rb[t4].z); Bs[q*4+3][row] = f2tf_f(rb[t4].w);
    }
    __syncthreads();

    for (int kb = 0; kb < DMODEL; kb += 32) {
        if (kb + 32 < DMODEL) {
#pragma unroll
            for (int t4 = 0; t4 < 4; t4++) {
                int idx = tid + t4 * 256;
                int row = idx & 127;
                int q = idx >> 7;
                ra[t4] = *(const float4*)&X[(size_t)(mBase + row) * DMODEL + kb + 32 + q * 4];
                rb[t4] = *(const float4*)&W[(size_t)(nBase + row) * DMODEL + kb + 32 + q * 4];
            }
        }
#pragma unroll
        for (int ks = 0; ks < 4; ks++) {
            int k0 = ks * 8 + t;
            uint32_t a[2][4], b[8][2];
#pragma unroll
            for (int mt = 0; mt < 2; mt++) {
                int m0 = wm + mt * 16 + g;
                a[mt][0] = __float_as_uint(As[k0][m0]);
                a[mt][1] = __float_as_uint(As[k0][m0 + 8]);
                a[mt][2] = __float_as_uint(As[k0 + 4][m0]);
                a[mt][3] = __float_as_uint(As[k0 + 4][m0 + 8]);
            }
#pragma unroll
            for (int nt = 0; nt < 8; nt++) {
                int n0 = wn + nt * 8 + g;
                b[nt][0] = __float_as_uint(Bs[k0][n0]);
                b[nt][1] = __float_as_uint(Bs[k0 + 4][n0]);
            }
#pragma unroll
            for (int mt = 0; mt < 2; mt++)
#pragma unroll
                for (int nt = 0; nt < 8; nt++)
                    mma8(acc[mt][nt], a[mt], b[nt]);
        }
        __syncthreads();
        if (kb + 32 < DMODEL) {
#pragma unroll
            for (int t4 = 0; t4 < 4; t4++) {
                int idx = tid + t4 * 256;
                int row = idx & 127;
                int q = idx >> 7;
                As[q*4+0][row] = f2tf_f(ra[t4].x); As[q*4+1][row] = f2tf_f(ra[t4].y);
                As[q*4+2][row] = f2tf_f(ra[t4].z); As[q*4+3][row] = f2tf_f(ra[t4].w);
                Bs[q*4+0][row] = f2tf_f(rb[t4].x); Bs[q*4+1][row] = f2tf_f(rb[t4].y);
                Bs[q*4+2][row] = f2tf_f(rb[t4].z); Bs[q*4+3][row] = f2tf_f(rb[t4].w);
            }
            __syncthreads();
        }
    }

    // Epilogue: bias + scatter to g_qkv[part][bh][s][hd]
#pragma unroll
    for (int mt = 0; mt < 2; mt++) {
#pragma unroll
        for (int half = 0; half < 2; half++) {
            int row = mBase + wm + mt * 16 + g + half * 8;
            int bb = row >> 11, s = row & 2047;
#pragma unroll
            for (int nt = 0; nt < 8; nt++) {
                int col = nBase + wn + nt * 8 + 2 * t;
                float v0 = acc[mt][nt][half * 2 + 0] + bias[col];
                float v1 = acc[mt][nt][half * 2 + 1] + bias[col + 1];
                int part = col >> 10, h = (col >> 6) & 15, hd = col & 63;
                size_t off = ((size_t)((part * BATCH + bb) * HEADS + h) * SEQ + s) * HDIM + hd;
                *(float2*)&g_qkv[off] = make_float2(v0, v1);
            }
        }
    }
}

// ---------------------------------------------------------------------------
// Kernel 2: per-head LayerNorm over Hd=64, in place on q and k parts.
// ---------------------------------------------------------------------------
__global__ __launch_bounds__(256) void ln_kernel(
    const float* __restrict__ qg, const float* __restrict__ qb,
    const float* __restrict__ kg, const float* __restrict__ kb)
{
    int warp = (blockIdx.x * blockDim.x + threadIdx.x) >> 5;
    int lane = threadIdx.x & 31;
    float* base = g_qkv + (size_t)warp * 64;
    int part = warp >> 16;
    const float* gamma = (part == 0) ? qg : kg;
    const float* beta  = (part == 0) ? qb : kb;

    float x0 = base[lane];
    float x1 = base[lane + 32];
    float s = x0 + x1;
#pragma unroll
    for (int o = 16; o >= 1; o >>= 1) s += __shfl_xor_sync(0xffffffffu, s, o);
    float mu = s * (1.0f / 64.0f);
    float d0 = x0 - mu, d1 = x1 - mu;
    float v = d0 * d0 + d1 * d1;
#pragma unroll
    for (int o = 16; o >= 1; o >>= 1) v += __shfl_xor_sync(0xffffffffu, v, o);
    float r = rsqrtf(v * (1.0f / 64.0f) + 1e-5f);
    base[lane]      = d0 * r * gamma[lane]      + beta[lane];
    base[lane + 32] = d1 * r * gamma[lane + 32] + beta[lane + 32];
}

// ---------------------------------------------------------------------------
// Kernel 3: flash attention, tf32 tensor cores. Br=128, Bc=64, 4 warps.
// Warp w: rows w*32..w*32+31 (2 m-tiles), all 64 keys (8 n-tiles).
// ---------------------------------------------------------------------------
#define QT_STRIDE 136
#define KT_STRIDE 72
#define VS_STRIDE 72
#define PS_STRIDE 68
#define ATTN_SMEM ((64*QT_STRIDE + 64*KT_STRIDE + 64*VS_STRIDE + 128*PS_STRIDE) * 4)

__global__ __launch_bounds__(128, 2) void attn_tf32_kernel()
{
    extern __shared__ float smem[];
    float* Qt = smem;                      // [hd 64][row 128+pad]
    float* Kt = Qt + 64 * QT_STRIDE;       // [hd 64][key 64+pad]
    float* Vs = Kt + 64 * KT_STRIDE;       // [key 64][hd 64+pad]
    float* Ps = Vs + 64 * VS_STRIDE;       // [row 128][key 64+pad]

    const int tid = threadIdx.x;
    const int warp = tid >> 5;
    const int lane = tid & 31;
    const int g = lane >> 2;
    const int t = lane & 3;
    const int wm = warp * 32;
    const int bh = blockIdx.y;
    const int qbase = blockIdx.x * 128;

    const float* Qg = g_qkv + (size_t)bh        * (SEQ * HDIM);
    const float* Kg = g_qkv + (size_t)(32 + bh) * (SEQ * HDIM);
    const float* Vg = g_qkv + (size_t)(64 + bh) * (SEQ * HDIM);

    // Load Q tile transposed, pre-scaled by 1/sqrt(64), tf32-rounded
#pragma unroll
    for (int tt = 0; tt < 16; tt++) {
        int idx = tid + tt * 128;
        int row = idx & 127;
        int q = idx >> 7;
        float4 v = *(const float4*)&Qg[(size_t)(qbase + row) * HDIM + q * 4];
        Qt[(q*4+0) * QT_STRIDE + row] = f2tf_f(v.x * 0.125f);
        Qt[(q*4+1) * QT_STRIDE + row] = f2tf_f(v.y * 0.125f);
        Qt[(q*4+2) * QT_STRIDE + row] = f2tf_f(v.z * 0.125f);
        Qt[(q*4+3) * QT_STRIDE + row] = f2tf_f(v.w * 0.125f);
    }

    float m_i[4], l_i[4], o[2][8][4];
#pragma unroll
    for (int i = 0; i < 4; i++) { m_i[i] = -1e30f; l_i[i] = 0.0f; }
#pragma unroll
    for (int mt = 0; mt < 2; mt++)
#pragma unroll
        for (int nt = 0; nt < 8; nt++)
#pragma unroll
            for (int i = 0; i < 4; i++) o[mt][nt][i] = 0.0f;

    for (int kt = 0; kt < SEQ; kt += 64) {
        __syncthreads();   // Qt ready (first iter) / prior PV done with Kt,Vs,Ps
        // K tile transposed: Kt[hd][key] — 64 keys x 16 quads = 1024 float4
#pragma unroll
        for (int tt = 0; tt < 8; tt++) {
            int idx = tid + tt * 128;
            int key = idx & 63;
            int q = idx >> 6;        // 0..15
            float4 v = *(const float4*)&Kg[(size_t)(kt + key) * HDIM + q * 4];
            Kt[(q*4+0) * KT_STRIDE + key] = f2tf_f(v.x);
            Kt[(q*4+1) * KT_STRIDE + key] = f2tf_f(v.y);
            Kt[(q*4+2) * KT_STRIDE + key] = f2tf_f(v.z);
            Kt[(q*4+3) * KT_STRIDE + key] = f2tf_f(v.w);
        }
        // V tile direct: Vs[key][hd]  (coalesced)
#pragma unroll
        for (int tt = 0; tt < 8; tt++) {
            int idx = tid + tt * 128;
            int key = idx >> 4;
            int q = idx & 15;
            float4 v = *(const float4*)&Vg[(size_t)(kt + key) * HDIM + q * 4];
            float4 w;
            w.x = f2tf_f(v.x); w.y = f2tf_f(v.y); w.z = f2tf_f(v.z); w.w = f2tf_f(v.w);
            *(float4*)&Vs[key * VS_STRIDE + q * 4] = w;
        }
        __syncthreads();

        // S = Q·Kᵀ (already scaled)
        float s[2][8][4];
#pragma unroll
        for (int mt = 0; mt < 2; mt++)
#pragma unroll
            for (int nt = 0; nt < 8; nt++)
#pragma unroll
                for (int i = 0; i < 4; i++) s[mt][nt][i] = 0.0f;

#pragma unroll
        for (int ks = 0; ks < 8; ks++) {
            int k0 = ks * 8 + t;
            uint32_t a[2][4], b[8][2];
#pragma unroll
            for (int mt = 0; mt < 2; mt++) {
                int m0 = wm + mt * 16 + g;
                a[mt][0] = __float_as_uint(Qt[k0 * QT_STRIDE + m0]);
                a[mt][1] = __float_as_uint(Qt[k0 * QT_STRIDE + m0 + 8]);
                a[mt][2] = __float_as_uint(Qt[(k0 + 4) * QT_STRIDE + m0]);
                a[mt][3] = __float_as_uint(Qt[(k0 + 4) * QT_STRIDE + m0 + 8]);
            }
#pragma unroll
            for (int nt = 0; nt < 8; nt++) {
                int n0 = nt * 8 + g;
                b[nt][0] = __float_as_uint(Kt[k0 * KT_STRIDE + n0]);
                b[nt][1] = __float_as_uint(Kt[(k0 + 4) * KT_STRIDE + n0]);
            }
#pragma unroll
            for (int mt = 0; mt < 2; mt++)
#pragma unroll
                for (int nt = 0; nt < 8; nt++)
                    mma8(s[mt][nt], a[mt], b[nt]);
        }

        // Online softmax per row-slot (mt, half)
#pragma unroll
        for (int mt = 0; mt < 2; mt++) {
#pragma unroll
            for (int half = 0; half < 2; half++) {
                int slot = mt * 2 + half;
                float mx = -1e30f;
#pragma unroll
                for (int nt = 0; nt < 8; nt++) {
                    mx = fmaxf(mx, s[mt][nt][half*2+0]);
                    mx = fmaxf(mx, s[mt][nt][half*2+1]);
                }
                mx = fmaxf(mx, __shfl_xor_sync(0xffffffffu, mx, 1));
                mx = fmaxf(mx, __shfl_xor_sync(0xffffffffu, mx, 2));
                float mnew = fmaxf(m_i[slot], mx);
                float alpha = __expf(m_i[slot] - mnew);
                float rs = 0.0f;
#pragma unroll
                for (int nt = 0; nt < 8; nt++) {
                    float p0 = __expf(s[mt][nt][half*2+0] - mnew);
                    float p1 = __expf(s[mt][nt][half*2+1] - mnew);
                    s[mt][nt][half*2+0] = p0;
                    s[mt][nt][half*2+1] = p1;
                    rs += p0 + p1;
                }
                rs += __shfl_xor_sync(0xffffffffu, rs, 1);
                rs += __shfl_xor_sync(0xffffffffu, rs, 2);
                l_i[slot] = l_i[slot] * alpha + rs;
                m_i[slot] = mnew;
#pragma unroll
                for (int nt = 0; nt < 8; nt++) {
                    o[mt][nt][half*2+0] *= alpha;
                    o[mt][nt][half*2+1] *= alpha;
                }
            }
        }

        // Store P[row][key]
#pragma unroll
        for (int mt = 0; mt < 2; mt++)
#pragma unroll
            for (int half = 0; half < 2; half++) {
                int row = wm + mt * 16 + g + half * 8;
#pragma unroll
                for (int nt = 0; nt < 8; nt++) {
                    float2 p = make_float2(f2tf_f(s[mt][nt][half*2+0]),
                                           f2tf_f(s[mt][nt][half*2+1]));
                    *(float2*)&Ps[row * PS_STRIDE + nt * 8 + 2 * t] = p;
                }
            }
        __syncthreads();

        // O += P·V
#pragma unroll
        for (int ks = 0; ks < 8; ks++) {
            int k0 = ks * 8 + t;
            uint32_t a[2][4], b[8][2];
#pragma unroll
            for (int mt = 0; mt < 2; mt++) {
                int m0 = wm + mt * 16 + g;
                a[mt][0] = __float_as_uint(Ps[m0 * PS_STRIDE + k0]);
                a[mt][1] = __float_as_uint(Ps[(m0 + 8) * PS_STRIDE + k0]);
                a[mt][2] = __float_as_uint(Ps[m0 * PS_STRIDE + k0 + 4]);
                a[mt][3] = __float_as_uint(Ps[(m0 + 8) * PS_STRIDE + k0 + 4]);
            }
#pragma unroll
            for (int nt = 0; nt < 8; nt++) {
                int n0 = nt * 8 + g;
                b[nt][0] = __float_as_uint(Vs[k0 * VS_STRIDE + n0]);
                b[nt][1] = __float_as_uint(Vs[(k0 + 4) * VS_STRIDE + n0]);
            }
#pragma unroll
            for (int mt = 0; mt < 2; mt++)
#pragma unroll
                for (int nt = 0; nt < 8; nt++)
                    mma8(o[mt][nt], a[mt], b[nt]);
        }
    }

    // Normalize, write out
    float* Og = g_attn + (size_t)bh * (SEQ * HDIM);
#pragma unroll
    for (int mt = 0; mt < 2; mt++)
#pragma unroll
        for (int half = 0; half < 2; half++) {
            int slot = mt * 2 + half;
            float inv = 1.0f / l_i[slot];
            int row = qbase + wm + mt * 16 + g + half * 8;
#pragma unroll
            for (int nt = 0; nt < 8; nt++) {
                float2 r = make_float2(o[mt][nt][half*2+0] * inv,
                                       o[mt][nt][half*2+1] * inv);
                *(float2*)&Og[(size_t)row * HDIM + nt * 8 + 2 * t] = r;
            }
        }
}

// ---------------------------------------------------------------------------
// Kernel 4: projection GEMM (tf32). A gathered from g_attn, out = A·Wpᵀ + bp.
// ---------------------------------------------------------------------------
__global__ __launch_bounds__(256, 1) void proj_gemm_tf32(
    const float* __restrict__ Wp, const float* __restrict__ bp,
    float* __restrict__ out)
{
    __shared__ float As[32][136];
    __shared__ float Bs[32][136];

    const int tid = threadIdx.x;
    const int warp = tid >> 5;
    const int lane = tid & 31;
    const int g = lane >> 2;
    const int t = lane & 3;
    const int wm = (warp >> 1) * 32;
    const int wn = (warp & 1) * 64;
    const int mBase = blockIdx.y * 128;
    const int nBase = blockIdx.x * 128;

    float acc[2][8][4];
#pragma unroll
    for (int mt = 0; mt < 2; mt++)
#pragma unroll
        for (int nt = 0; nt < 8; nt++)
#pragma unroll
            for (int i = 0; i < 4; i++) acc[mt][nt][i] = 0.0f;

    float4 ra[4], rb[4];
    auto loadA = [&](int kb, int t4) -> float4 {
        int idx = tid + t4 * 256;
        int row = idx & 127;
        int q = idx >> 7;
        int m = mBase + row;
        int k = kb + q * 4;
        int b = m >> 11, s = m & 2047;
        int h = k >> 6, hd = k & 63;
        return *(const float4*)&g_attn[((size_t)(b * HEADS + h) * SEQ + s) * HDIM + hd];
    };

#pragma unroll
    for (int t4 = 0; t4 < 4; t4++) {
        int idx = tid + t4 * 256;
        int row = idx & 127;
        int q = idx >> 7;
        ra[t4] = loadA(0, t4);
        rb[t4] = *(const float4*)&Wp[(size_t)(nBase + row) * DMODEL + q * 4];
    }
#pragma unroll
    for (int t4 = 0; t4 < 4; t4++) {
        int idx = tid + t4 * 256;
        int row = idx & 127;
        int q = idx >> 7;
        As[q*4+0][row] = f2tf_f(ra[t4].x); As[q*4+1][row] = f2tf_f(ra[t4].y);
        As[q*4+2][row] = f2tf_f(ra[t4].z); As[q*4+3][row] = f2tf_f(ra[t4].w);
        Bs[q*4+0][row] = f2tf_f(rb[t4].x); Bs[q*4+1][row] = f2tf_f(rb[t4].y);
        Bs[q*4+2][row] = f2tf_f(rb[t4].z); Bs[q*4+3][row] = f2tf_f(rb[t4].w);
    }
    __syncthreads();

    for (int kb = 0; kb < DMODEL; kb += 32) {
        if (kb + 32 < DMODEL) {
#pragma unroll
            for (int t4 = 0; t4 < 4; t4++) {
                int idx = tid + t4 * 256;
                int row = idx & 127;
                int q = idx >> 7;
                ra[t4] = loadA(kb + 32, t4);
                rb[t4] = *(const float4*)&Wp[(size_t)(nBase + row) * DMODEL + kb + 32 + q * 4];
            }
        }
#pragma unroll
        for (int ks = 0; ks < 4; ks++) {
            int k0 = ks * 8 + t;
            uint32_t a[2][4], b[8][2];
#pragma unroll
            for (int mt = 0; mt < 2; mt++) {
                int m0 = wm + mt * 16 + g;
                a[mt][0] = __float_as_uint(As[k0][m0]);
                a[mt][1] = __float_as_uint(As[k0][m0 + 8]);
                a[mt][2] = __float_as_uint(As[k0 + 4][m0]);
                a[mt][3] = __float_as_uint(As[k0 + 4][m0 + 8]);
            }
#pragma unroll
            for (int nt = 0; nt < 8; nt++) {
                int n0 = wn + nt * 8 + g;
                b[nt][0] = __float_as_uint(Bs[k0][n0]);
                b[nt][1] = __float_as_uint(Bs[k0 + 4][n0]);
            }
#pragma unroll
            for (int mt = 0; mt < 2; mt++)
#pragma unroll
                for (int nt = 0; nt < 8; nt++)
                    mma8(acc[mt][nt], a[mt], b[nt]);
        }
        __syncthreads();
        if (kb + 32 < DMODEL) {
#pragma unroll
            for (int t4 = 0; t4 < 4; t4++) {
                int idx = tid + t4 * 256;
                int row = idx & 127;
                int q = idx >> 7;
                As[q*4+0][row] = f2tf_f(ra[t4].x); As[q*4+1][row] = f2tf_f(ra[t4].y);
                As[q*4+2][row] = f2tf_f(ra[t4].z); As[q*4+3][row] = f2tf_f(ra[t4].w);
                Bs[q*4+0][row] = f2tf_f(rb[t4].x); Bs[q*4+1][row] = f2tf_f(rb[t4].y);
                Bs[q*4+2][row] = f2tf_f(rb[t4].z); Bs[q*4+3][row] = f2tf_f(rb[t4].w);
            }
            __syncthreads();
        }
    }

#pragma unroll
    for (int mt = 0; mt < 2; mt++)
#pragma unroll
        for (int half = 0; half < 2; half++) {
            int row = mBase + wm + mt * 16 + g + half * 8;
#pragma unroll
            for (int nt = 0; nt < 8; nt++) {
                int col = nBase + wn + nt * 8 + 2 * t;
                float2 r = make_float2(acc[mt][nt][half*2+0] + bp[col],
                                       acc[mt][nt][half*2+1] + bp[col + 1]);
                *(float2*)&out[(size_t)row * DMODEL + col] = r;
            }
        }
}

// ---------------------------------------------------------------------------
// Launch. Inputs: 0:x 1:w_qkv 2:b_qkv 3:w_proj 4:b_proj 5:qg 6:qb 7:kg 8:kb
// ---------------------------------------------------------------------------
extern "C" void kernel_launch(void* const* d_in, const int* in_sizes, int n_in,
                              void* d_out, int out_size)
{
    const float* x      = (const float*)d_in[0];
    const float* w_qkv  = (const float*)d_in[1];
    const float* b_qkv  = (const float*)d_in[2];
    const float* w_proj = (const float*)d_in[3];
    const float* b_proj = (const float*)d_in[4];
    const float* q_g    = (const float*)d_in[5];
    const float* q_b    = (const float*)d_in[6];
    const float* k_g    = (const float*)d_in[7];
    const float* k_b    = (const float*)d_in[8];
    float* out = (float*)d_out;

    cudaFuncSetAttribute(attn_tf32_kernel,
                         cudaFuncAttributeMaxDynamicSharedMemorySize, ATTN_SMEM);

    dim3 g1(NQKV / 128, MROWS / 128);   // (24, 32)
    qkv_gemm_tf32<<<g1, 256>>>(x, w_qkv, b_qkv);

    ln_kernel<<<131072 / 8, 256>>>(q_g, q_b, k_g, k_b);

    dim3 g3(SEQ / 128, BATCH * HEADS);  // (16, 32)
    attn_tf32_kernel<<<g3, 128, ATTN_SMEM>>>();

    dim3 g4(DMODEL / 128, MROWS / 128); // (8, 32)
    proj_gemm_tf32<<<g4, 256>>>(w_proj, b_proj, out);
}

// round 4
// speedup vs baseline: 2.4793x; 1.2335x over previous
#include <cuda_runtime.h>
#include <math.h>
#include <stdint.h>

#define BATCH 2
#define SEQ   2048
#define DMODEL 1024
#define HEADS 16
#define HDIM  64
#define MROWS (BATCH * SEQ)          // 4096
#define NQKV  (3 * DMODEL)           // 3072

__device__ float g_qkv[(size_t)3 * BATCH * HEADS * SEQ * HDIM];
__device__ float g_attn[(size_t)BATCH * HEADS * SEQ * HDIM];

__device__ __forceinline__ float f2tf_f(float x) {
    uint32_t r;
    asm("cvt.rna.tf32.f32 %0, %1;" : "=r"(r) : "f"(x));
    return __uint_as_float(r);
}
#define FU(x) __float_as_uint(x)
#define F4E(v, e) (((const float*)&(v))[e])

// D = A(16x8 row) * B(8x8 col) + D, tf32 in, fp32 accum
__device__ __forceinline__ void mma8(float* c, const uint32_t* a, const uint32_t* b) {
    asm volatile(
        "mma.sync.aligned.m16n8k8.row.col.f32.tf32.tf32.f32 "
        "{%0,%1,%2,%3}, {%4,%5,%6,%7}, {%8,%9}, {%0,%1,%2,%3};"
        : "+f"(c[0]), "+f"(c[1]), "+f"(c[2]), "+f"(c[3])
        : "r"(a[0]), "r"(a[1]), "r"(a[2]), "r"(a[3]), "r"(b[0]), "r"(b[1]));
}

// Permutation within a 32-wide k block: k = ks*8 + t + 4h  ->  pos = t*8 + ks*2 + h
// For a gmem float4 at k = 4q + j (q in 0..7): pos = j*8 + (q>>1)*2 + (q&1)
// For a 64-wide k: two 32-blocks, pos += (k>>5)*32.
__device__ __forceinline__ int perm64c(int c) {
    return ((c >> 5) << 5) + (c & 3) * 8 + ((c >> 3) & 3) * 2 + ((c >> 2) & 1);
}

// ---------------------------------------------------------------------------
// Kernel 1: QKV GEMM. CTA tile 128x64, k-tile 32, 256 thr = 8 warps (4m x 2n),
// warp 32x32. Output scattered to g_qkv[part][bh][s][hd].
// ---------------------------------------------------------------------------
__global__ __launch_bounds__(256, 2) void qkv_gemm_tf32(
    const float* __restrict__ X, const float* __restrict__ W,
    const float* __restrict__ bias)
{
    __shared__ float As[128 * 36];
    __shared__ float Bs[64 * 36];

    const int tid = threadIdx.x;
    const int warp = tid >> 5, lane = tid & 31;
    const int g = lane >> 2, t = lane & 3;
    const int wm = (warp >> 1) * 32, wn = (warp & 1) * 32;
    const int mBase = blockIdx.y * 128, nBase = blockIdx.x * 64;

    float acc[2][4][4];
#pragma unroll
    for (int mt = 0; mt < 2; mt++)
#pragma unroll
        for (int nt = 0; nt < 4; nt++)
#pragma unroll
            for (int i = 0; i < 4; i++) acc[mt][nt][i] = 0.0f;

    float4 ra[4], rb[2];
#pragma unroll
    for (int i = 0; i < 4; i++) {
        int idx = tid + i * 256, row = idx >> 3, q = idx & 7;
        ra[i] = *(const float4*)&X[(size_t)(mBase + row) * DMODEL + q * 4];
    }
#pragma unroll
    for (int i = 0; i < 2; i++) {
        int idx = tid + i * 256, row = idx >> 3, q = idx & 7;
        rb[i] = *(const float4*)&W[(size_t)(nBase + row) * DMODEL + q * 4];
    }
#pragma unroll
    for (int i = 0; i < 4; i++) {
        int idx = tid + i * 256, row = idx >> 3, q = idx & 7;
        int base = row * 36 + (q >> 1) * 2 + (q & 1);
        As[base + 0]  = f2tf_f(ra[i].x); As[base + 8]  = f2tf_f(ra[i].y);
        As[base + 16] = f2tf_f(ra[i].z); As[base + 24] = f2tf_f(ra[i].w);
    }
#pragma unroll
    for (int i = 0; i < 2; i++) {
        int idx = tid + i * 256, row = idx >> 3, q = idx & 7;
        int base = row * 36 + (q >> 1) * 2 + (q & 1);
        Bs[base + 0]  = f2tf_f(rb[i].x); Bs[base + 8]  = f2tf_f(rb[i].y);
        Bs[base + 16] = f2tf_f(rb[i].z); Bs[base + 24] = f2tf_f(rb[i].w);
    }
    __syncthreads();

    for (int kb = 0; kb < DMODEL; kb += 32) {
        if (kb + 32 < DMODEL) {
#pragma unroll
            for (int i = 0; i < 4; i++) {
                int idx = tid + i * 256, row = idx >> 3, q = idx & 7;
                ra[i] = *(const float4*)&X[(size_t)(mBase + row) * DMODEL + kb + 32 + q * 4];
            }
#pragma unroll
            for (int i = 0; i < 2; i++) {
                int idx = tid + i * 256, row = idx >> 3, q = idx & 7;
                rb[i] = *(const float4*)&W[(size_t)(nBase + row) * DMODEL + kb + 32 + q * 4];
            }
        }
#pragma unroll
        for (int kh = 0; kh < 2; kh++) {
            float4 a4[2][2], b4[4];
#pragma unroll
            for (int mt = 0; mt < 2; mt++) {
                a4[mt][0] = *(const float4*)&As[(wm + mt * 16 + g) * 36 + t * 8 + kh * 4];
                a4[mt][1] = *(const float4*)&As[(wm + mt * 16 + g + 8) * 36 + t * 8 + kh * 4];
            }
#pragma unroll
            for (int nt = 0; nt < 4; nt++)
                b4[nt] = *(const float4*)&Bs[(wn + nt * 8 + g) * 36 + t * 8 + kh * 4];
#pragma unroll
            for (int ks2 = 0; ks2 < 2; ks2++) {
                const int e = ks2 * 2;
#pragma unroll
                for (int mt = 0; mt < 2; mt++) {
                    uint32_t a[4] = { FU(F4E(a4[mt][0], e)),     FU(F4E(a4[mt][1], e)),
                                      FU(F4E(a4[mt][0], e + 1)), FU(F4E(a4[mt][1], e + 1)) };
#pragma unroll
                    for (int nt = 0; nt < 4; nt++) {
                        uint32_t b[2] = { FU(F4E(b4[nt], e)), FU(F4E(b4[nt], e + 1)) };
                        mma8(acc[mt][nt], a, b);
                    }
                }
            }
        }
        __syncthreads();
        if (kb + 32 < DMODEL) {
#pragma unroll
            for (int i = 0; i < 4; i++) {
                int idx = tid + i * 256, row = idx >> 3, q = idx & 7;
                int base = row * 36 + (q >> 1) * 2 + (q & 1);
                As[base + 0]  = f2tf_f(ra[i].x); As[base + 8]  = f2tf_f(ra[i].y);
                As[base + 16] = f2tf_f(ra[i].z); As[base + 24] = f2tf_f(ra[i].w);
            }
#pragma unroll
            for (int i = 0; i < 2; i++) {
                int idx = tid + i * 256, row = idx >> 3, q = idx & 7;
                int base = row * 36 + (q >> 1) * 2 + (q & 1);
                Bs[base + 0]  = f2tf_f(rb[i].x); Bs[base + 8]  = f2tf_f(rb[i].y);
                Bs[base + 16] = f2tf_f(rb[i].z); Bs[base + 24] = f2tf_f(rb[i].w);
            }
            __syncthreads();
        }
    }

#pragma unroll
    for (int mt = 0; mt < 2; mt++)
#pragma unroll
        for (int half = 0; half < 2; half++) {
            int row = mBase + wm + mt * 16 + g + half * 8;
            int bb = row >> 11, s = row & 2047;
#pragma unroll
            for (int nt = 0; nt < 4; nt++) {
                int col = nBase + wn + nt * 8 + 2 * t;
                float v0 = acc[mt][nt][half * 2 + 0] + bias[col];
                float v1 = acc[mt][nt][half * 2 + 1] + bias[col + 1];
                int part = col >> 10, h = (col >> 6) & 15, hd = col & 63;
                size_t off = ((size_t)((part * BATCH + bb) * HEADS + h) * SEQ + s) * HDIM + hd;
                *(float2*)&g_qkv[off] = make_float2(v0, v1);
            }
        }
}

// ---------------------------------------------------------------------------
// Kernel 2: per-head LayerNorm (Hd=64) in place on q/k parts.
// ---------------------------------------------------------------------------
__global__ __launch_bounds__(256) void ln_kernel(
    const float* __restrict__ qg, const float* __restrict__ qb,
    const float* __restrict__ kg, const float* __restrict__ kb)
{
    int warp = (blockIdx.x * blockDim.x + threadIdx.x) >> 5;
    int lane = threadIdx.x & 31;
    float* base = g_qkv + (size_t)warp * 64;
    int part = warp >> 16;
    const float* gamma = (part == 0) ? qg : kg;
    const float* beta  = (part == 0) ? qb : kb;

    float x0 = base[lane], x1 = base[lane + 32];
    float s = x0 + x1;
#pragma unroll
    for (int o = 16; o >= 1; o >>= 1) s += __shfl_xor_sync(0xffffffffu, s, o);
    float mu = s * (1.0f / 64.0f);
    float d0 = x0 - mu, d1 = x1 - mu;
    float v = d0 * d0 + d1 * d1;
#pragma unroll
    for (int o = 16; o >= 1; o >>= 1) v += __shfl_xor_sync(0xffffffffu, v, o);
    float r = rsqrtf(v * (1.0f / 64.0f) + 1e-5f);
    base[lane]      = d0 * r * gamma[lane]      + beta[lane];
    base[lane + 32] = d1 * r * gamma[lane + 32] + beta[lane + 32];
}

// ---------------------------------------------------------------------------
// Kernel 3: flash attention, tf32. Br=128, Bc=64, 256 thr = 8 warps,
// warp tile 16 rows x 64 keys. Occupancy 2 CTAs/SM (104 KB smem).
// Layouts (k-permuted, stride 68): Qs[row][hd], Ks[key][hd], Vt[hd][key], Ps[row][key]
// ---------------------------------------------------------------------------
#define AT_STR 68
#define ATTN_SMEM ((128 * AT_STR + 64 * AT_STR + 64 * AT_STR + 128 * AT_STR) * 4)

__global__ __launch_bounds__(256, 2) void attn_tf32_kernel()
{
    extern __shared__ float smem[];
    float* Qs = smem;                    // [128][68]
    float* Ks = Qs + 128 * AT_STR;       // [64][68]
    float* Vt = Ks + 64 * AT_STR;        // [64][68]  (hd-major)
    float* Ps = Vt + 64 * AT_STR;        // [128][68]

    const int tid = threadIdx.x;
    const int warp = tid >> 5, lane = tid & 31;
    const int g = lane >> 2, t = lane & 3;
    const int wm = warp * 16;
    const int bh = blockIdx.y;
    const int qbase = blockIdx.x * 128;

    const float* Qg = g_qkv + (size_t)bh        * (SEQ * HDIM);
    const float* Kg = g_qkv + (size_t)(32 + bh) * (SEQ * HDIM);
    const float* Vg = g_qkv + (size_t)(64 + bh) * (SEQ * HDIM);

    // Q tile: pre-scaled, tf32-rounded, permuted
#pragma unroll
    for (int i = 0; i < 8; i++) {
        int idx = tid + i * 256, row = idx >> 4, q = idx & 15;
        float4 v = *(const float4*)&Qg[(size_t)(qbase + row) * HDIM + q * 4];
        int base = row * AT_STR + (q >> 3) * 32 + ((q & 7) >> 1) * 2 + (q & 1);
        Qs[base + 0]  = f2tf_f(v.x * 0.125f); Qs[base + 8]  = f2tf_f(v.y * 0.125f);
        Qs[base + 16] = f2tf_f(v.z * 0.125f); Qs[base + 24] = f2tf_f(v.w * 0.125f);
    }

    float m_i[2] = {-1e30f, -1e30f}, l_i[2] = {0.0f, 0.0f};
    float o[8][4];
#pragma unroll
    for (int nt = 0; nt < 8; nt++)
#pragma unroll
        for (int i = 0; i < 4; i++) o[nt][i] = 0.0f;

    for (int kt = 0; kt < SEQ; kt += 64) {
        __syncthreads();   // Qt ready / prior iter done with Ks,Vt
        // K tile: [key][hd-perm]
#pragma unroll
        for (int i = 0; i < 4; i++) {
            int idx = tid + i * 256, key = idx >> 4, q = idx & 15;
            float4 v = *(const float4*)&Kg[(size_t)(kt + key) * HDIM + q * 4];
            int base = key * AT_STR + (q >> 3) * 32 + ((q & 7) >> 1) * 2 + (q & 1);
            Ks[base + 0]  = f2tf_f(v.x); Ks[base + 8]  = f2tf_f(v.y);
            Ks[base + 16] = f2tf_f(v.z); Ks[base + 24] = f2tf_f(v.w);
        }
        // V tile transposed: Vt[hd][key-perm]
#pragma unroll
        for (int i = 0; i < 4; i++) {
            int idx = tid + i * 256, key = idx >> 4, q = idx & 15;
            float4 v = *(const float4*)&Vg[(size_t)(kt + key) * HDIM + q * 4];
            int pc = perm64c(key);
            Vt[(q * 4 + 0) * AT_STR + pc] = f2tf_f(v.x);
            Vt[(q * 4 + 1) * AT_STR + pc] = f2tf_f(v.y);
            Vt[(q * 4 + 2) * AT_STR + pc] = f2tf_f(v.z);
            Vt[(q * 4 + 3) * AT_STR + pc] = f2tf_f(v.w);
        }
        __syncthreads();

        // S = Q·Kᵀ
        float s[8][4];
#pragma unroll
        for (int nt = 0; nt < 8; nt++)
#pragma unroll
            for (int i = 0; i < 4; i++) s[nt][i] = 0.0f;

#pragma unroll
        for (int sb = 0; sb < 2; sb++)
#pragma unroll
            for (int kh = 0; kh < 2; kh++) {
                int off = sb * 32 + t * 8 + kh * 4;
                float4 qa0 = *(const float4*)&Qs[(wm + g) * AT_STR + off];
                float4 qa1 = *(const float4*)&Qs[(wm + g + 8) * AT_STR + off];
                float4 kb4[8];
#pragma unroll
                for (int nt = 0; nt < 8; nt++)
                    kb4[nt] = *(const float4*)&Ks[(nt * 8 + g) * AT_STR + off];
#pragma unroll
                for (int ks2 = 0; ks2 < 2; ks2++) {
                    const int e = ks2 * 2;
                    uint32_t a[4] = { FU(F4E(qa0, e)), FU(F4E(qa1, e)),
                                      FU(F4E(qa0, e + 1)), FU(F4E(qa1, e + 1)) };
#pragma unroll
                    for (int nt = 0; nt < 8; nt++) {
                        uint32_t b[2] = { FU(F4E(kb4[nt], e)), FU(F4E(kb4[nt], e + 1)) };
                        mma8(s[nt], a, b);
                    }
                }
            }

        // Online softmax: slot0 = row wm+g, slot1 = row wm+g+8 (quad reduce over t)
#pragma unroll
        for (int slot = 0; slot < 2; slot++) {
            float mx = -1e30f;
#pragma unroll
            for (int nt = 0; nt < 8; nt++) {
                mx = fmaxf(mx, s[nt][slot * 2 + 0]);
                mx = fmaxf(mx, s[nt][slot * 2 + 1]);
            }
            mx = fmaxf(mx, __shfl_xor_sync(0xffffffffu, mx, 1));
            mx = fmaxf(mx, __shfl_xor_sync(0xffffffffu, mx, 2));
            float mnew = fmaxf(m_i[slot], mx);
            float alpha = __expf(m_i[slot] - mnew);
            float rs = 0.0f;
#pragma unroll
            for (int nt = 0; nt < 8; nt++) {
                float p0 = __expf(s[nt][slot * 2 + 0] - mnew);
                float p1 = __expf(s[nt][slot * 2 + 1] - mnew);
                s[nt][slot * 2 + 0] = p0;
                s[nt][slot * 2 + 1] = p1;
                rs += p0 + p1;
            }
            rs += __shfl_xor_sync(0xffffffffu, rs, 1);
            rs += __shfl_xor_sync(0xffffffffu, rs, 2);
            l_i[slot] = l_i[slot] * alpha + rs;
            m_i[slot] = mnew;
#pragma unroll
            for (int nt = 0; nt < 8; nt++) {
                o[nt][slot * 2 + 0] *= alpha;
                o[nt][slot * 2 + 1] *= alpha;
            }
        }

        // Ps[row][key-perm] — warp-private rows, only syncwarp needed
#pragma unroll
        for (int slot = 0; slot < 2; slot++) {
            int row = wm + g + slot * 8;
#pragma unroll
            for (int nt = 0; nt < 8; nt++) {
#pragma unroll
                for (int j = 0; j < 2; j++) {
                    int c = nt * 8 + 2 * t + j;
                    Ps[row * AT_STR + perm64c(c)] = f2tf_f(s[nt][slot * 2 + j]);
                }
            }
        }
        __syncwarp();

        // O += P·V
#pragma unroll
        for (int sb = 0; sb < 2; sb++)
#pragma unroll
            for (int kh = 0; kh < 2; kh++) {
                int off = sb * 32 + t * 8 + kh * 4;
                float4 pa0 = *(const float4*)&Ps[(wm + g) * AT_STR + off];
                float4 pa1 = *(const float4*)&Ps[(wm + g + 8) * AT_STR + off];
                float4 vb4[8];
#pragma unroll
                for (int nt = 0; nt < 8; nt++)
                    vb4[nt] = *(const float4*)&Vt[(nt * 8 + g) * AT_STR + off];
#pragma unroll
                for (int ks2 = 0; ks2 < 2; ks2++) {
                    const int e = ks2 * 2;
                    uint32_t a[4] = { FU(F4E(pa0, e)), FU(F4E(pa1, e)),
                                      FU(F4E(pa0, e + 1)), FU(F4E(pa1, e + 1)) };
#pragma unroll
                    for (int nt = 0; nt < 8; nt++) {
                        uint32_t b[2] = { FU(F4E(vb4[nt], e)), FU(F4E(vb4[nt], e + 1)) };
                        mma8(o[nt], a, b);
                    }
                }
            }
    }

    // Normalize + write
    float* Og = g_attn + (size_t)bh * (SEQ * HDIM);
#pragma unroll
    for (int slot = 0; slot < 2; slot++) {
        float inv = 1.0f / l_i[slot];
        int row = qbase + wm + g + slot * 8;
#pragma unroll
        for (int nt = 0; nt < 8; nt++) {
            float2 r = make_float2(o[nt][slot * 2 + 0] * inv,
                                   o[nt][slot * 2 + 1] * inv);
            *(float2*)&Og[(size_t)row * HDIM + nt * 8 + 2 * t] = r;
        }
    }
}

// ---------------------------------------------------------------------------
// Kernel 4: projection GEMM. CTA 128x64, A gathered from g_attn.
// ---------------------------------------------------------------------------
__global__ __launch_bounds__(256, 2) void proj_gemm_tf32(
    const float* __restrict__ Wp, const float* __restrict__ bp,
    float* __restrict__ out)
{
    __shared__ float As[128 * 36];
    __shared__ float Bs[64 * 36];

    const int tid = threadIdx.x;
    const int warp = tid >> 5, lane = tid & 31;
    const int g = lane >> 2, t = lane & 3;
    const int wm = (warp >> 1) * 32, wn = (warp & 1) * 32;
    const int mBase = blockIdx.y * 128, nBase = blockIdx.x * 64;

    float acc[2][4][4];
#pragma unroll
    for (int mt = 0; mt < 2; mt++)
#pragma unroll
        for (int nt = 0; nt < 4; nt++)
#pragma unroll
            for (int i = 0; i < 4; i++) acc[mt][nt][i] = 0.0f;

    float4 ra[4], rb[2];
    auto loadA = [&](int kb, int i) -> float4 {
        int idx = tid + i * 256, row = idx >> 3, q = idx & 7;
        int m = mBase + row, k = kb + q * 4;
        int b = m >> 11, s = m & 2047, h = k >> 6, hd = k & 63;
        return *(const float4*)&g_attn[((size_t)(b * HEADS + h) * SEQ + s) * HDIM + hd];
    };

#pragma unroll
    for (int i = 0; i < 4; i++) ra[i] = loadA(0, i);
#pragma unroll
    for (int i = 0; i < 2; i++) {
        int idx = tid + i * 256, row = idx >> 3, q = idx & 7;
        rb[i] = *(const float4*)&Wp[(size_t)(nBase + row) * DMODEL + q * 4];
    }
#pragma unroll
    for (int i = 0; i < 4; i++) {
        int idx = tid + i * 256, row = idx >> 3, q = idx & 7;
        int base = row * 36 + (q >> 1) * 2 + (q & 1);
        As[base + 0]  = f2tf_f(ra[i].x); As[base + 8]  = f2tf_f(ra[i].y);
        As[base + 16] = f2tf_f(ra[i].z); As[base + 24] = f2tf_f(ra[i].w);
    }
#pragma unroll
    for (int i = 0; i < 2; i++) {
        int idx = tid + i * 256, row = idx >> 3, q = idx & 7;
        int base = row * 36 + (q >> 1) * 2 + (q & 1);
        Bs[base + 0]  = f2tf_f(rb[i].x); Bs[base + 8]  = f2tf_f(rb[i].y);
        Bs[base + 16] = f2tf_f(rb[i].z); Bs[base + 24] = f2tf_f(rb[i].w);
    }
    __syncthreads();

    for (int kb = 0; kb < DMODEL; kb += 32) {
        if (kb + 32 < DMODEL) {
#pragma unroll
            for (int i = 0; i < 4; i++) ra[i] = loadA(kb + 32, i);
#pragma unroll
            for (int i = 0; i < 2; i++) {
                int idx = tid + i * 256, row = idx >> 3, q = idx & 7;
                rb[i] = *(const float4*)&Wp[(size_t)(nBase + row) * DMODEL + kb + 32 + q * 4];
            }
        }
#pragma unroll
        for (int kh = 0; kh < 2; kh++) {
            float4 a4[2][2], b4[4];
#pragma unroll
            for (int mt = 0; mt < 2; mt++) {
                a4[mt][0] = *(const float4*)&As[(wm + mt * 16 + g) * 36 + t * 8 + kh * 4];
                a4[mt][1] = *(const float4*)&As[(wm + mt * 16 + g + 8) * 36 + t * 8 + kh * 4];
            }
#pragma unroll
            for (int nt = 0; nt < 4; nt++)
                b4[nt] = *(const float4*)&Bs[(wn + nt * 8 + g) * 36 + t * 8 + kh * 4];
#pragma unroll
            for (int ks2 = 0; ks2 < 2; ks2++) {
                const int e = ks2 * 2;
#pragma unroll
                for (int mt = 0; mt < 2; mt++) {
                    uint32_t a[4] = { FU(F4E(a4[mt][0], e)),     FU(F4E(a4[mt][1], e)),
                                      FU(F4E(a4[mt][0], e + 1)), FU(F4E(a4[mt][1], e + 1)) };
#pragma unroll
                    for (int nt = 0; nt < 4; nt++) {
                        uint32_t b[2] = { FU(F4E(b4[nt], e)), FU(F4E(b4[nt], e + 1)) };
                        mma8(acc[mt][nt], a, b);
                    }
                }
            }
        }
        __syncthreads();
        if (kb + 32 < DMODEL) {
#pragma unroll
            for (int i = 0; i < 4; i++) {
                int idx = tid + i * 256, row = idx >> 3, q = idx & 7;
                int base = row * 36 + (q >> 1) * 2 + (q & 1);
                As[base + 0]  = f2tf_f(ra[i].x); As[base + 8]  = f2tf_f(ra[i].y);
                As[base + 16] = f2tf_f(ra[i].z); As[base + 24] = f2tf_f(ra[i].w);
            }
#pragma unroll
            for (int i = 0; i < 2; i++) {
                int idx = tid + i * 256, row = idx >> 3, q = idx & 7;
                int base = row * 36 + (q >> 1) * 2 + (q & 1);
                Bs[base + 0]  = f2tf_f(rb[i].x); Bs[base + 8]  = f2tf_f(rb[i].y);
                Bs[base + 16] = f2tf_f(rb[i].z); Bs[base + 24] = f2tf_f(rb[i].w);
            }
            __syncthreads();
        }
    }

#pragma unroll
    for (int mt = 0; mt < 2; mt++)
#pragma unroll
        for (int half = 0; half < 2; half++) {
            int row = mBase + wm + mt * 16 + g + half * 8;
#pragma unroll
            for (int nt = 0; nt < 4; nt++) {
                int col = nBase + wn + nt * 8 + 2 * t;
                float2 r = make_float2(acc[mt][nt][half * 2 + 0] + bp[col],
                                       acc[mt][nt][half * 2 + 1] + bp[col + 1]);
                *(float2*)&out[(size_t)row * DMODEL + col] = r;
            }
        }
}

// ---------------------------------------------------------------------------
// Launch. Inputs: 0:x 1:w_qkv 2:b_qkv 3:w_proj 4:b_proj 5:qg 6:qb 7:kg 8:kb
// ---------------------------------------------------------------------------
extern "C" void kernel_launch(void* const* d_in, const int* in_sizes, int n_in,
                              void* d_out, int out_size)
{
    const float* x      = (const float*)d_in[0];
    const float* w_qkv  = (const float*)d_in[1];
    const float* b_qkv  = (const float*)d_in[2];
    const float* w_proj = (const float*)d_in[3];
    const float* b_proj = (const float*)d_in[4];
    const float* q_g    = (const float*)d_in[5];
    const float* q_b    = (const float*)d_in[6];
    const float* k_g    = (const float*)d_in[7];
    const float* k_b    = (const float*)d_in[8];
    float* out = (float*)d_out;

    cudaFuncSetAttribute(attn_tf32_kernel,
                         cudaFuncAttributeMaxDynamicSharedMemorySize, ATTN_SMEM);

    dim3 g1(NQKV / 64, MROWS / 128);    // (48, 32)
    qkv_gemm_tf32<<<g1, 256>>>(x, w_qkv, b_qkv);

    ln_kernel<<<131072 / 8, 256>>>(q_g, q_b, k_g, k_b);

    dim3 g3(SEQ / 128, BATCH * HEADS);  // (16, 32)
    attn_tf32_kernel<<<g3, 256, ATTN_SMEM>>>();

    dim3 g4(DMODEL / 64, MROWS / 128);  // (16, 32)
    proj_gemm_tf32<<<g4, 256>>>(w_proj, b_proj, out);
}